// round 17
// baseline (speedup 1.0000x reference)
#include <cuda_runtime.h>
#include <cuda_fp16.h>

#define Bsz 4
#define S   2048
#define D   128
#define H   8
#define DK  16
#define BH  (Bsz*H)
#define NSL 128            // colpart sub-slabs (16-q granularity)

typedef unsigned long long u64;
typedef unsigned int u32;

// 0.25 * log2(e): folded into Q at projection time so attention uses raw ex2
#define SCQ 0.36067376022224086f

// ---- scratch (no device allocations allowed) ----
__device__ float g_Q[BH*S*DK];                // pre-scaled by SCQ (fp32)
__device__ float g_K[BH*S*DK];
__device__ float g_V[BH*S*DK];
__device__ __half g_QhT[BH*DK*S];             // Qhat fp16, [bh][k][q] (2 MB)
__device__ __half g_Kh[BH*S*DK];              // K fp16, [bh][m][k] (2 MB)
__device__ float g_negb[BH*S];                // 8 - maxQn*||K[m]|| (neg CS bias)
__device__ __half g_E[(size_t)BH*S*S];        // 256 MB, [bh][m][q]
__device__ float g_colpart[NSL*BH*S];         // per-16q colsum partials (33.5 MB)
__device__ __half g_VTa[BH*DK*S];             // bucketed (V*rc*2^10)^T, |.|<2^14
__device__ __half g_VTb[BH*DK*S];             // [2^14,2^29) stored *2^-15
__device__ __half g_VTc[BH*DK*S];             // >=2^29 stored *2^-30
__device__ float g_maxqn[BH];
__device__ float g_head[Bsz*S*D];

// ---- helpers ----
__device__ __forceinline__ void ffma2(u64& d, u64 a, u64 b){
    asm("fma.rn.f32x2 %0, %1, %2, %0;" : "+l"(d) : "l"(a), "l"(b));
}
__device__ __forceinline__ u64 dup2(float x){
    u64 r; asm("mov.b64 %0, {%1, %1};" : "=l"(r) : "f"(x)); return r;
}
__device__ __forceinline__ float hsum2(u64 v){
    float lo, hi; asm("mov.b64 {%0, %1}, %2;" : "=f"(lo), "=f"(hi) : "l"(v));
    return lo + hi;
}
__device__ __forceinline__ float2 unpk(u64 v){
    float2 r; asm("mov.b64 {%0, %1}, %2;" : "=f"(r.x), "=f"(r.y) : "l"(v));
    return r;
}
__device__ __forceinline__ float ex2f(float x){
    float r; asm("ex2.approx.f32 %0, %1;" : "=f"(r) : "f"(x)); return r;
}
__device__ __forceinline__ u64 lds64(const float* p){
    return *reinterpret_cast<const u64*>(p);
}
__device__ __forceinline__ u64 ldg64(const float* p){
    return *reinterpret_cast<const u64*>(p);
}
__device__ __forceinline__ u32 smem_u32(const void* p){
    u32 a;
    asm("{ .reg .u64 t; cvta.to.shared.u64 t, %1; cvt.u32.u64 %0, t; }"
        : "=r"(a) : "l"(p));
    return a;
}
__device__ __forceinline__ void cp16(u32 dst, const void* src){
    asm volatile("cp.async.ca.shared.global [%0], [%1], 16;"
                 :: "r"(dst), "l"(src));
}

// ============================================================
// Kernel 1: Q/K/V projections. grid (B*S/64, 3), 128 threads.
// ============================================================
__global__ void proj_kernel(const float* __restrict__ x,
                            const float* __restrict__ wq,
                            const float* __restrict__ wk,
                            const float* __restrict__ wv) {
    __shared__ float xs[64][132];
    __shared__ float wsT[16][132];
    const int t = threadIdx.x;       // 128
    const int row0 = blockIdx.x * 64;
    const int pj = blockIdx.y;
    const float* W0 = (pj == 0 ? wq : pj == 1 ? wk : wv);
    float* dst = (pj == 0 ? g_Q : pj == 1 ? g_K : g_V);
    const float oscale = (pj == 0) ? SCQ : 1.0f;

    #pragma unroll
    for (int k = 0; k < 16; k++) {
        int idx = t + k*128;
        int r = idx >> 5, q4 = idx & 31;
        *reinterpret_cast<float4*>(&xs[r][q4*4]) =
            *reinterpret_cast<const float4*>(x + (row0 + r)*D + q4*4);
    }

    const int rg = t >> 3, cg = t & 7;
    for (int h = 0; h < H; h++) {
        __syncthreads();
        #pragma unroll
        for (int k = 0; k < 4; k++) {
            int idx = t + k*128;
            int d = idx >> 2, c4 = idx & 3;
            float4 v = *reinterpret_cast<const float4*>(W0 + h*D*DK + d*DK + c4*4);
            wsT[c4*4+0][d] = v.x; wsT[c4*4+1][d] = v.y;
            wsT[c4*4+2][d] = v.z; wsT[c4*4+3][d] = v.w;
        }
        __syncthreads();

        u64 acc[4][2] = {};
        #pragma unroll 8
        for (int d = 0; d < D; d += 2) {
            u64 w0 = lds64(&wsT[cg][d]);
            u64 w1 = lds64(&wsT[cg+8][d]);
            #pragma unroll
            for (int i = 0; i < 4; i++) {
                u64 xv = lds64(&xs[rg*4+i][d]);
                ffma2(acc[i][0], xv, w0);
                ffma2(acc[i][1], xv, w1);
            }
        }
        #pragma unroll
        for (int i = 0; i < 4; i++) {
            int grow = row0 + rg*4 + i;
            int b = grow >> 11, s = grow & (S-1);
            float* o = dst + ((b*H + h)*S + s)*DK;
            o[cg]   = hsum2(acc[i][0]) * oscale;
            o[cg+8] = hsum2(acc[i][1]) * oscale;
        }
    }
}

// ============================================================
// Kernel 1b: maxQnorm[bh] = max_q ||Qhat[q]||. grid BH, 256 threads.
// ============================================================
__global__ void __launch_bounds__(256) qnorm_kernel() {
    __shared__ float red[256];
    const int bh = blockIdx.x, t = threadIdx.x;
    const float* Qb = g_Q + bh*S*DK;
    float mx = 0.f;
    for (int r = t; r < S; r += 256) {
        u64 a = 0;
        #pragma unroll
        for (int j = 0; j < 8; j++) {
            u64 q = ldg64(Qb + r*DK + 2*j);
            ffma2(a, q, q);
        }
        mx = fmaxf(mx, hsum2(a));
    }
    red[t] = mx;
    __syncthreads();
    #pragma unroll
    for (int s2 = 128; s2; s2 >>= 1) {
        if (t < s2) red[t] = fmaxf(red[t], red[t + s2]);
        __syncthreads();
    }
    if (t == 0) g_maxqn[bh] = sqrtf(red[0]);
}

// ============================================================
// Kernel 1c: prep fp16 operands + neg CS bias. grid BH*S/256, 256 thr.
// ============================================================
__global__ void __launch_bounds__(256) prep_kernel() {
    const int row = blockIdx.x*256 + threadIdx.x;   // bh*S + i
    const int bh = row >> 11, i = row & (S-1);
    const float* Qr = g_Q + row*DK;
    #pragma unroll
    for (int k = 0; k < DK; k++)
        g_QhT[(bh*DK + k)*S + i] = __float2half(Qr[k]);

    const float* Kr = g_K + row*DK;
    float nrm = 0.f;
    __half2 kh[8];
    #pragma unroll
    for (int k = 0; k < 8; k++) {
        float2 v = unpk(ldg64(Kr + 2*k));
        nrm = fmaf(v.x, v.x, nrm);
        nrm = fmaf(v.y, v.y, nrm);
        kh[k] = __floats2half2_rn(v.x, v.y);
    }
    *reinterpret_cast<uint4*>(g_Kh + row*DK)     = *reinterpret_cast<uint4*>(&kh[0]);
    *reinterpret_cast<uint4*>(g_Kh + row*DK + 8) = *reinterpret_cast<uint4*>(&kh[4]);
    g_negb[row] = 8.0f - sqrtf(nrm) * g_maxqn[bh];
}

// ============================================================
// Kernel 2: scores via HMMA m16n8k16 (R16-proven, 131us).
// grid (S/64, BH), 128 threads.
// ============================================================
__global__ void __launch_bounds__(128) scoresE_kernel() {
    __shared__ __align__(16) __half QhT[16][72];
    __shared__ __align__(16) __half Khs[128][16];
    __shared__ float bs[128];
    const int t = threadIdx.x, w = t >> 5, lane = t & 31;
    const int g = lane >> 2, tq = lane & 3;
    const int bh = blockIdx.y, q0 = blockIdx.x * 64;
    const __half* Kh = g_Kh + bh*S*DK;
    const float* nb = g_negb + bh*S;
    __half* Eb = g_E + (size_t)bh*S*S;
    float* cp = g_colpart + (blockIdx.x*4 + w)*(BH*S) + bh*S;

    {
        int r = t >> 3, c8 = t & 7;
        *reinterpret_cast<uint4*>(&QhT[r][c8*8]) =
            *reinterpret_cast<const uint4*>(g_QhT + (bh*DK + r)*S + q0 + c8*8);
    }
    __syncthreads();

    u32 qa0, qa1, qa2, qa3;
    {
        const int lrow = (lane & 7) + ((lane >> 4) << 3);
        const u32 addr = smem_u32(QhT) + lrow*144 + w*32 + ((lane >> 3) & 1)*16;
        asm volatile(
            "ldmatrix.sync.aligned.m8n8.x4.trans.shared.b16 {%0,%1,%2,%3}, [%4];"
            : "=r"(qa0), "=r"(qa1), "=r"(qa2), "=r"(qa3) : "r"(addr));
    }

    for (int m0 = 0; m0 < S; m0 += 128) {
        __syncthreads();
        *reinterpret_cast<uint4*>(&Khs[t][0]) =
            *reinterpret_cast<const uint4*>(Kh + (m0 + t)*DK);
        *reinterpret_cast<uint4*>(&Khs[t][8]) =
            *reinterpret_cast<const uint4*>(Kh + (m0 + t)*DK + 8);
        bs[t] = nb[m0 + t];
        __syncthreads();

        #pragma unroll 4
        for (int step = 0; step < 16; step++) {
            const int mk8 = step*8;
            u32 b0 = *reinterpret_cast<const u32*>(&Khs[mk8 + g][2*tq]);
            u32 b1 = *reinterpret_cast<const u32*>(&Khs[mk8 + g][2*tq + 8]);
            float nb0 = bs[mk8 + 2*tq];
            float nb1 = bs[mk8 + 2*tq + 1];
            float c0, c1, c2, c3;
            asm volatile(
                "mma.sync.aligned.m16n8k16.row.col.f32.f16.f16.f32 "
                "{%0,%1,%2,%3}, {%4,%5,%6,%7}, {%8,%9}, {%10,%11,%10,%11};"
                : "=f"(c0), "=f"(c1), "=f"(c2), "=f"(c3)
                : "r"(qa0), "r"(qa1), "r"(qa2), "r"(qa3),
                  "r"(b0), "r"(b1), "f"(nb0), "f"(nb1));
            float e0 = ex2f(c0), e1 = ex2f(c1);
            float e2 = ex2f(c2), e3 = ex2f(c3);
            __half2 h0 = __floats2half2_rn(e0, e1);
            __half2 h1 = __floats2half2_rn(e2, e3);
            u32 t0, t1;
            asm("movmatrix.sync.aligned.m8n8.trans.b16 %0, %1;"
                : "=r"(t0) : "r"(*reinterpret_cast<u32*>(&h0)));
            asm("movmatrix.sync.aligned.m8n8.trans.b16 %0, %1;"
                : "=r"(t1) : "r"(*reinterpret_cast<u32*>(&h1)));
            const int mg = m0 + mk8 + g;
            __half* Erow = Eb + (size_t)mg*S + q0 + w*16;
            *reinterpret_cast<u32*>(Erow + 2*tq)     = t0;
            *reinterpret_cast<u32*>(Erow + 2*tq + 8) = t1;
            float2 f0 = __half22float2(*reinterpret_cast<__half2*>(&t0));
            float2 f1 = __half22float2(*reinterpret_cast<__half2*>(&t1));
            float ps = (f0.x + f0.y) + (f1.x + f1.y);
            ps += __shfl_xor_sync(0xffffffffu, ps, 1);
            ps += __shfl_xor_sync(0xffffffffu, ps, 2);
            if (tq == 0) cp[mg] = ps;
        }
    }
}

// ============================================================
// Kernel 2b: reduce 128 colsum sub-slabs -> EXACT bucketed VT
// (validated R12/13): Vp' = V*(2^10/colsum); a:|.|<2^14,
// b:[2^14,2^29)*2^-15, c:>=2^29 *2^-30. grid BH*S/256, 256 thr.
// ============================================================
__global__ void __launch_bounds__(256) colredVp3_kernel() {
    const int row = blockIdx.x*256 + threadIdx.x;   // bh*S + m
    float s = 0.f;
    #pragma unroll 8
    for (int sl = 0; sl < NSL; sl++) s += g_colpart[sl*(BH*S) + row];
    const float rc = (s > 0.f) ? __frcp_rn(s) * 1024.0f : 0.f;
    const int bh = row >> 11, m = row & (S-1);
    const float* Vr = g_V + row*DK;
    #pragma unroll
    for (int v = 0; v < DK; v++) {
        const float vp = Vr[v] * rc;
        const float av = fabsf(vp);
        const float a = (av < 16384.0f) ? vp : 0.f;
        const float b = (av >= 16384.0f && av < 536870912.0f)
                            ? vp * (1.0f/32768.0f) : 0.f;
        const float c = (av >= 536870912.0f) ? vp * (1.0f/1073741824.0f) : 0.f;
        const size_t o = (size_t)bh*DK*S + (size_t)v*S + m;
        g_VTa[o] = __float2half(a);
        g_VTb[o] = __float2half(b);
        g_VTc[o] = __float2half(c);
    }
}

// ============================================================
// Kernel 3: out = E^T @ Vp via HMMA + cp.async double buffering.
// grid (S/128, BH), 256 threads (8 warps; warp w owns q [16w,16w+16)
// of the 128-q tile). E chunks 64m x 128q (16KB) prefetched into
// alternating buffers while the previous chunk computes -> DRAM-bound.
// 3 exact range buckets; epilogue (Ca + 2^15 Cb + 2^30 Cc) * 2^-10.
// ============================================================
__global__ void __launch_bounds__(256) ev_kernel() {
    __shared__ __align__(16) char Es[2][64*272];   // 2 x 17KB
    const int t = threadIdx.x, w = t >> 5, lane = t & 31;
    const int bh = blockIdx.y, q0 = blockIdx.x * 128;
    const __half* Eb = g_E + (size_t)bh*S*S;
    const size_t bt0 = (size_t)bh*DK*S;
    const int g = lane >> 2, tq = lane & 3;
    const int lrow  = (lane & 7) + ((lane >> 4) << 3);
    const int lqoff = 32*w + ((lane >> 3) & 1)*16;
    const u32 es0 = smem_u32(Es);

    float accA[8] = {}, accB[8] = {}, accC[8] = {};

    // prefetch chunk 0
    {
        #pragma unroll
        for (int pp = 0; pp < 4; pp++) {
            int idx = t + pp*256;
            int r = idx >> 4, pc = idx & 15;
            cp16(es0 + r*272 + pc*16,
                 Eb + (size_t)r*S + q0 + pc*8);
        }
        asm volatile("cp.async.commit_group;");
    }

    for (int c = 0; c < 32; c++) {
        const int m0 = c*64;
        if (c + 1 < 32) {                          // prefetch next chunk
            const u32 base = es0 + ((c+1) & 1)*17408;
            #pragma unroll
            for (int pp = 0; pp < 4; pp++) {
                int idx = t + pp*256;
                int r = idx >> 4, pc = idx & 15;
                cp16(base + r*272 + pc*16,
                     Eb + (size_t)(m0 + 64 + r)*S + q0 + pc*8);
            }
            asm volatile("cp.async.commit_group;");
            asm volatile("cp.async.wait_group 1;");
        } else {
            asm volatile("cp.async.wait_group 0;");
        }
        __syncthreads();                           // chunk c ready for all

        const u32 buf = es0 + (c & 1)*17408;
        #pragma unroll
        for (int ck = 0; ck < 4; ck++) {
            u32 a0, a1, a2, a3;
            u32 addr = buf + (ck*16 + lrow)*272 + lqoff;
            asm volatile(
                "ldmatrix.sync.aligned.m8n8.x4.trans.shared.b16 {%0,%1,%2,%3}, [%4];"
                : "=r"(a0), "=r"(a1), "=r"(a2), "=r"(a3) : "r"(addr));
            const int mk = m0 + ck*16;
            const size_t i00 = bt0 + (size_t)g*S     + mk + 2*tq;
            const size_t i10 = bt0 + (size_t)(g+8)*S + mk + 2*tq;
            #pragma unroll
            for (int bk = 0; bk < 3; bk++) {
                const __half* Bt = (bk == 0) ? g_VTa : (bk == 1) ? g_VTb : g_VTc;
                float* ac = (bk == 0) ? accA : (bk == 1) ? accB : accC;
                u32 b00 = *reinterpret_cast<const u32*>(Bt + i00);
                u32 b01 = *reinterpret_cast<const u32*>(Bt + i00 + 8);
                u32 b10 = *reinterpret_cast<const u32*>(Bt + i10);
                u32 b11 = *reinterpret_cast<const u32*>(Bt + i10 + 8);
                asm volatile(
                    "mma.sync.aligned.m16n8k16.row.col.f32.f16.f16.f32 "
                    "{%0,%1,%2,%3}, {%4,%5,%6,%7}, {%8,%9}, {%0,%1,%2,%3};"
                    : "+f"(ac[0]), "+f"(ac[1]), "+f"(ac[2]), "+f"(ac[3])
                    : "r"(a0), "r"(a1), "r"(a2), "r"(a3), "r"(b00), "r"(b01));
                asm volatile(
                    "mma.sync.aligned.m16n8k16.row.col.f32.f16.f16.f32 "
                    "{%0,%1,%2,%3}, {%4,%5,%6,%7}, {%8,%9}, {%0,%1,%2,%3};"
                    : "+f"(ac[4]), "+f"(ac[5]), "+f"(ac[6]), "+f"(ac[7])
                    : "r"(a0), "r"(a1), "r"(a2), "r"(a3), "r"(b10), "r"(b11));
            }
        }
        __syncthreads();                           // before buffer reuse
    }

    const int b = bh >> 3, h = bh & 7;
    float o[8];
    #pragma unroll
    for (int i = 0; i < 8; i++)
        o[i] = (accA[i] + 32768.0f*accB[i] + 1073741824.0f*accC[i])
               * (1.0f/1024.0f);
    const int q = q0 + 16*w + g;
    float* d0 = g_head + (b*S + q)*D     + h*DK;
    float* d1 = g_head + (b*S + q + 8)*D + h*DK;
    *reinterpret_cast<float2*>(d0 + 2*tq)     = make_float2(o[0], o[1]);
    *reinterpret_cast<float2*>(d0 + 8 + 2*tq) = make_float2(o[4], o[5]);
    *reinterpret_cast<float2*>(d1 + 2*tq)     = make_float2(o[2], o[3]);
    *reinterpret_cast<float2*>(d1 + 8 + 2*tq) = make_float2(o[6], o[7]);
}

// ============================================================
// Kernel 4: out = head[B*S,128] @ w_o[128,128]. grid 256, 256 thr.
// ============================================================
__global__ void final_proj_kernel(const float* __restrict__ wo,
                                  float* __restrict__ out) {
    __shared__ float hsT[128][34];
    const int t = threadIdx.x;
    const int row0 = blockIdx.x * 32;

    #pragma unroll
    for (int k = 0; k < 4; k++) {
        int idx = t + k*256;
        int r = idx >> 5, j4 = idx & 31;
        float4 v = *reinterpret_cast<const float4*>(g_head + (row0 + r)*D + j4*4);
        hsT[j4*4+0][r] = v.x; hsT[j4*4+1][r] = v.y;
        hsT[j4*4+2][r] = v.z; hsT[j4*4+3][r] = v.w;
    }
    __syncthreads();

    const int c = t & 127, rh = t >> 7;
    u64 acc[8] = {};
    #pragma unroll 4
    for (int j = 0; j < D; j++) {
        u64 w = dup2(wo[j*D + c]);
        #pragma unroll
        for (int p = 0; p < 8; p++)
            ffma2(acc[p], lds64(&hsT[j][rh*16 + 2*p]), w);
    }
    #pragma unroll
    for (int p = 0; p < 8; p++) {
        float2 v = unpk(acc[p]);
        int r = row0 + rh*16 + 2*p;
        out[r*D + c]     = v.x;
        out[(r+1)*D + c] = v.y;
    }
}

// ============================================================
extern "C" void kernel_launch(void* const* d_in, const int* in_sizes, int n_in,
                              void* d_out, int out_size) {
    const float* x  = (const float*)d_in[0];
    const float* wq = (const float*)d_in[1];
    const float* wk = (const float*)d_in[2];
    const float* wv = (const float*)d_in[3];
    const float* wo = (const float*)d_in[4];
    float* out = (float*)d_out;

    proj_kernel      <<< dim3(Bsz*S/64, 3), 128 >>>(x, wq, wk, wv);
    qnorm_kernel     <<< BH,                256 >>>();
    prep_kernel      <<< BH*S/256,          256 >>>();
    scoresE_kernel   <<< dim3(S/64, BH),    128 >>>();
    colredVp3_kernel <<< BH*S/256,          256 >>>();
    ev_kernel        <<< dim3(S/128, BH),   256 >>>();
    final_proj_kernel<<< Bsz*S/32,          256 >>>(wo, out);
}